// round 10
// baseline (speedup 1.0000x reference)
#include <cuda_runtime.h>
#include <cstdint>

// WeightedBCELoss: out[b,s] = (labels[b,s]==0) ? -log(1-pred) : -weight[b]*log(pred)
// pred [4096,8192] f32, labels [4096,8192] i32, weight [4096] f32.
//
// R10 = R4 (certified best: ncu 53.2-54.7us, 82.9-84.9% DRAM over 3 runs) with
// the one untested variable changed: 512-thread blocks (grid 8192). Per-thread
// shape identical (2 float4, 4 front-batched 16B loads, MLP_p1=4); threads/SM
// identical (4096). Only CTA count / scheduling overhead halves.
//   - uniform per-block weight broadcast (block = 1024 f4 = half row, row=blk>>1)
//   - __ldcs reads + __stcs writes (stwt falsified), single __logf/element

#define BATCH 4096
#define SENT  8192
#define V4_PER_ROW (SENT / 4)   // 2048
#define THREADS 512

__device__ __forceinline__ float bce_term(float p, int l, float w) {
    float a = (l == 0) ? (1.0f - p) : p;
    float s = (l == 0) ? 1.0f : w;
    return -s * __logf(a);
}

__global__ __launch_bounds__(THREADS, 4)
void wbce_kernel(const float4* __restrict__ pred,
                 const int4*   __restrict__ labels,
                 const float*  __restrict__ weight,
                 float4*       __restrict__ out)
{
    // Block covers float4 range [blk*1024, blk*1024+1024) — half of one
    // 2048-f4 row. row = blk >> 1. Weight is uniform per block.
    const int   row = blockIdx.x >> 1;
    const float w   = __ldg(&weight[row]);

    const long i0 = (long)blockIdx.x * 1024 + threadIdx.x;
    const long i1 = i0 + 512;

    // Front-batched: 4 independent 16B loads (MLP_p1 = 4, measured sweet spot).
    float4 p0 = __ldcs(&pred[i0]);
    float4 p1 = __ldcs(&pred[i1]);
    int4   l0 = __ldcs(&labels[i0]);
    int4   l1 = __ldcs(&labels[i1]);

    float4 o0, o1;
    o0.x = bce_term(p0.x, l0.x, w);
    o0.y = bce_term(p0.y, l0.y, w);
    o0.z = bce_term(p0.z, l0.z, w);
    o0.w = bce_term(p0.w, l0.w, w);
    o1.x = bce_term(p1.x, l1.x, w);
    o1.y = bce_term(p1.y, l1.y, w);
    o1.z = bce_term(p1.z, l1.z, w);
    o1.w = bce_term(p1.w, l1.w, w);

    __stcs(&out[i0], o0);
    __stcs(&out[i1], o1);
}

extern "C" void kernel_launch(void* const* d_in, const int* in_sizes, int n_in,
                              void* d_out, int out_size)
{
    const float4* pred   = (const float4*)d_in[0];
    const int4*   labels = (const int4*)d_in[1];
    const float*  weight = (const float*)d_in[2];
    float4*       out    = (float4*)d_out;

    const int total_v4 = BATCH * V4_PER_ROW;   // 8,388,608
    wbce_kernel<<<total_v4 / 1024, THREADS>>>(pred, labels, weight, out);
}